// round 1
// baseline (speedup 1.0000x reference)
#include <cuda_runtime.h>
#include <cstdint>

#define NN 8192
#define DD 256
#define DELTA_F 1.0f

#define BM 128
#define BN 128
#define BK 32
#define PADW 132   // 128 + 4 floats: keeps 16B alignment for LDS.128, breaks store conflicts partially

// Scratch (no allocations allowed -> __device__ globals)
__device__ unsigned long long g_pos[NN];
__device__ unsigned long long g_neg[NN];
__device__ float g_sq[NN];
__device__ int   g_tgt[NN];
__device__ int   g_is32;   // 1 if targets buffer is int32, 0 if int64

// Monotonic unsigned key for float ordering
__device__ __forceinline__ unsigned int fkey(float f) {
    unsigned int u = __float_as_uint(f);
    return (u & 0x80000000u) ? ~u : (u | 0x80000000u);
}

// ---------------------------------------------------------------------------
// k0: reset flags/output
__global__ void zero_kernel(float* out) {
    g_is32 = 0;
    out[0] = 0.0f;
}

// k1: per-row sum of squares, init best arrays, probe targets dtype
__global__ void prep_kernel(const float* __restrict__ q, const void* __restrict__ tgt_raw) {
    int gtid = blockIdx.x * blockDim.x + threadIdx.x;
    int warp = gtid >> 5;
    int lane = gtid & 31;

    // dtype probe: if int64 (values < 2^31, nonneg), every odd int32 word is 0.
    if (gtid < NN / 2) {
        int hi = ((const int*)tgt_raw)[2 * gtid + 1];
        if (hi != 0) atomicOr(&g_is32, 1);
    }

    if (warp < NN) {
        const float* row = q + warp * DD;
        float s = 0.0f;
        #pragma unroll
        for (int k = lane; k < DD; k += 32) { float v = row[k]; s += v * v; }
        #pragma unroll
        for (int o = 16; o; o >>= 1) s += __shfl_xor_sync(0xffffffffu, s, o);
        if (lane == 0) {
            g_sq[warp] = s;
            // init = pack(value=+0.0f, idx=0): matches jnp.argmax on an all-zero masked row
            unsigned long long init = ((unsigned long long)0x80000000u << 32) | 0xFFFFFFFFull;
            g_pos[warp] = init;
            g_neg[warp] = init;
        }
    }
}

// k2: normalize targets to int32 scratch
__global__ void convert_kernel(const void* __restrict__ tgt_raw) {
    int i = blockIdx.x * blockDim.x + threadIdx.x;
    if (i >= NN) return;
    if (g_is32) g_tgt[i] = ((const int*)tgt_raw)[i];
    else        g_tgt[i] = (int)(((const long long*)tgt_raw)[i]);
}

// ---------------------------------------------------------------------------
// k3: tiled Gram + fused masked row-argmax
__global__ __launch_bounds__(256, 2)
void tile_kernel(const float* __restrict__ q) {
    __shared__ float As[BK][PADW];
    __shared__ float Bs[BK][PADW];
    __shared__ float sqi[BM], sqj[BN];
    __shared__ int   ti[BM], tj[BN];
    __shared__ unsigned long long posS[BM], negS[BM];

    const int ib = blockIdx.y * BM;
    const int jb = blockIdx.x * BN;
    const int tid = threadIdx.x;
    const int tx = tid & 15;   // column group 0..15
    const int ty = tid >> 4;   // row group 0..15

    if (tid < BM) {
        sqi[tid] = g_sq[ib + tid];
        ti[tid]  = g_tgt[ib + tid];
        posS[tid] = 0ull;
        negS[tid] = 0ull;
    } else {
        int t = tid - BM;
        sqj[t] = g_sq[jb + t];
        tj[t]  = g_tgt[jb + t];
    }

    float acc[8][8];
    #pragma unroll
    for (int a = 0; a < 8; a++)
        #pragma unroll
        for (int b = 0; b < 8; b++) acc[a][b] = 0.0f;

    for (int k0 = 0; k0 < DD; k0 += BK) {
        __syncthreads();
        // load 128x32 fp32 tiles of A and B (both are rows of Q), transposed to [BK][BM]
        #pragma unroll
        for (int s = 0; s < 4; s++) {
            int f   = tid + 256 * s;    // 0..1023
            int row = f >> 3;
            int kq  = f & 7;
            float4 va = *(const float4*)(q + (size_t)(ib + row) * DD + k0 + kq * 4);
            float4 vb = *(const float4*)(q + (size_t)(jb + row) * DD + k0 + kq * 4);
            As[kq * 4 + 0][row] = va.x; As[kq * 4 + 1][row] = va.y;
            As[kq * 4 + 2][row] = va.z; As[kq * 4 + 3][row] = va.w;
            Bs[kq * 4 + 0][row] = vb.x; Bs[kq * 4 + 1][row] = vb.y;
            Bs[kq * 4 + 2][row] = vb.z; Bs[kq * 4 + 3][row] = vb.w;
        }
        __syncthreads();
        #pragma unroll
        for (int k = 0; k < BK; k++) {
            float ra[8], rb[8];
            *(float4*)&ra[0] = *(const float4*)&As[k][ty * 4];
            *(float4*)&ra[4] = *(const float4*)&As[k][64 + ty * 4];
            *(float4*)&rb[0] = *(const float4*)&Bs[k][tx * 4];
            *(float4*)&rb[4] = *(const float4*)&Bs[k][64 + tx * 4];
            #pragma unroll
            for (int a = 0; a < 8; a++)
                #pragma unroll
                for (int b = 0; b < 8; b++)
                    acc[a][b] = fmaf(ra[a], rb[b], acc[a][b]);
        }
    }
    __syncthreads();

    // epilogue: distances + masked per-row max (packed value|~index for argmax tie-break)
    #pragma unroll
    for (int a = 0; a < 8; a++) {
        int rl = ((a & 4) << 4) + ty * 4 + (a & 3);   // a<4: ty*4+a ; a>=4: 64+ty*4+(a-4)
        int gi = ib + rl;
        float si = sqi[rl];
        int tgti = ti[rl];
        unsigned long long bp = 0ull, bn = 0ull;
        #pragma unroll
        for (int b = 0; b < 8; b++) {
            int cl = ((b & 4) << 4) + tx * 4 + (b & 3);
            int gj = jb + cl;
            if (gi == gj) continue;                    // diagonal = -inf
            float dist = si + sqj[cl] - 2.0f * acc[a][b];
            unsigned long long packed =
                ((unsigned long long)fkey(dist) << 32) | (unsigned int)(~gj);
            if (tgti == tj[cl]) { if (packed > bp) bp = packed; }
            else                { if (packed > bn) bn = packed; }
        }
        if (bp) atomicMax(&posS[rl], bp);
        if (bn) atomicMax(&negS[rl], bn);
    }
    __syncthreads();
    if (tid < BM) {
        if (posS[tid]) atomicMax(&g_pos[ib + tid], posS[tid]);
        if (negS[tid]) atomicMax(&g_neg[ib + tid], negS[tid]);
    }
}

// ---------------------------------------------------------------------------
// k4: gather hardest pos/neg, recompute exact distances like reference, mean loss
__global__ void loss_kernel(const float* __restrict__ q, float* __restrict__ out) {
    int gtid = blockIdx.x * blockDim.x + threadIdx.x;
    int warp = gtid >> 5;
    int lane = gtid & 31;
    int wInB = threadIdx.x >> 5;
    __shared__ float bsum[8];

    float loss = 0.0f;
    if (warp < NN) {
        unsigned int pidx = ~(unsigned int)(g_pos[warp] & 0xFFFFFFFFull);
        unsigned int nidx = ~(unsigned int)(g_neg[warp] & 0xFFFFFFFFull);
        const float* qi = q + (size_t)warp * DD;
        const float* qp = q + (size_t)pidx * DD;
        const float* qn = q + (size_t)nidx * DD;
        float dp = 0.0f, dn = 0.0f;
        #pragma unroll
        for (int k = lane; k < DD; k += 32) {
            float x = qi[k];
            float a = x - qp[k]; dp = fmaf(a, a, dp);
            float b = x - qn[k]; dn = fmaf(b, b, dn);
        }
        #pragma unroll
        for (int o = 16; o; o >>= 1) {
            dp += __shfl_xor_sync(0xffffffffu, dp, o);
            dn += __shfl_xor_sync(0xffffffffu, dn, o);
        }
        loss = fmaxf(0.0f, DELTA_F - dp + dn);
    }
    if (lane == 0) bsum[wInB] = loss;
    __syncthreads();
    if (threadIdx.x == 0) {
        float s = 0.0f;
        #pragma unroll
        for (int w = 0; w < 8; w++) s += bsum[w];
        atomicAdd(out, s * (1.0f / (float)NN));
    }
}

// ---------------------------------------------------------------------------
extern "C" void kernel_launch(void* const* d_in, const int* in_sizes, int n_in,
                              void* d_out, int out_size) {
    const float* q   = (const float*)d_in[0];
    const void*  tgt = d_in[1];
    float* out = (float*)d_out;

    zero_kernel<<<1, 1>>>(out);
    prep_kernel<<<NN / 8, 256>>>(q, tgt);          // 8192 warps: sq + init + dtype probe
    convert_kernel<<<NN / 256, 256>>>(tgt);
    dim3 grid(NN / BN, NN / BM);                   // 64 x 64 tiles
    tile_kernel<<<grid, 256>>>(q);
    loss_kernel<<<NN / 8, 256>>>(q, out);
}

// round 4
// speedup vs baseline: 5.0103x; 5.0103x over previous
#include <cuda_runtime.h>
#include <cuda_bf16.h>
#include <cstdint>

#define NN 8192
#define DD 256
#define DELTA_F 1.0f

// ---------------- device globals (no runtime allocation allowed) ----------
__device__ unsigned long long g_pos[NN];
__device__ unsigned long long g_neg[NN];
__device__ float g_sq[NN];
__device__ int   g_tgt[NN];
__device__ int   g_is32;
__device__ __nv_bfloat16 g_qbf[NN * DD];   // 4MB bf16 copy of queries

// ---------------- helpers ---------------------------------------------------
__device__ __forceinline__ unsigned int fkey(float f) {
    unsigned int u = __float_as_uint(f);
    return (u & 0x80000000u) ? ~u : (u | 0x80000000u);
}

#define CP_ASYNC16(dst, src) \
    asm volatile("cp.async.cg.shared.global [%0], [%1], 16;" :: "r"(dst), "l"(src))
#define CP_COMMIT()  asm volatile("cp.async.commit_group;" ::: "memory")
#define CP_WAIT1()   asm volatile("cp.async.wait_group 1;" ::: "memory")
#define CP_WAIT0()   asm volatile("cp.async.wait_group 0;" ::: "memory")

#define LDSM4(r0, r1, r2, r3, a) \
    asm volatile("ldmatrix.sync.aligned.m8n8.x4.shared.b16 {%0,%1,%2,%3}, [%4];" \
                 : "=r"(r0), "=r"(r1), "=r"(r2), "=r"(r3) : "r"(a))

__device__ __forceinline__ void mma16816(float* c, uint32_t a0, uint32_t a1,
                                         uint32_t a2, uint32_t a3,
                                         uint32_t b0, uint32_t b1) {
    asm volatile("mma.sync.aligned.m16n8k16.row.col.f32.bf16.bf16.f32 "
                 "{%0,%1,%2,%3},{%4,%5,%6,%7},{%8,%9},{%0,%1,%2,%3};"
                 : "+f"(c[0]), "+f"(c[1]), "+f"(c[2]), "+f"(c[3])
                 : "r"(a0), "r"(a1), "r"(a2), "r"(a3), "r"(b0), "r"(b1));
}

// ---------------- small kernels --------------------------------------------
__global__ void zero_kernel(float* out) { g_is32 = 0; out[0] = 0.0f; }

__global__ void prep_kernel(const float* __restrict__ q, const void* __restrict__ tgt_raw) {
    int gtid = blockIdx.x * blockDim.x + threadIdx.x;
    int warp = gtid >> 5, lane = gtid & 31;
    if (gtid < NN / 2) {
        int hi = ((const int*)tgt_raw)[2 * gtid + 1];
        if (hi != 0) atomicOr(&g_is32, 1);
    }
    if (warp < NN) {
        const float* row = q + warp * DD;
        float s = 0.0f;
        #pragma unroll
        for (int k = lane; k < DD; k += 32) { float v = row[k]; s += v * v; }
        #pragma unroll
        for (int o = 16; o; o >>= 1) s += __shfl_xor_sync(0xffffffffu, s, o);
        if (lane == 0) {
            g_sq[warp] = s;
            unsigned long long init = ((unsigned long long)0x80000000u << 32) | 0xFFFFFFFFull;
            g_pos[warp] = init;
            g_neg[warp] = init;
        }
    }
}

__global__ void tgt_kernel(const void* __restrict__ tgt_raw) {
    int i = blockIdx.x * blockDim.x + threadIdx.x;
    if (i >= NN) return;
    if (g_is32) g_tgt[i] = ((const int*)tgt_raw)[i];
    else        g_tgt[i] = (int)(((const long long*)tgt_raw)[i]);
}

__global__ void qconv_kernel(const float* __restrict__ q) {
    int i = blockIdx.x * blockDim.x + threadIdx.x;     // one float4 each
    float4 v = ((const float4*)q)[i];
    __nv_bfloat162 p0 = __floats2bfloat162_rn(v.x, v.y);
    __nv_bfloat162 p1 = __floats2bfloat162_rn(v.z, v.w);
    uint2 o; o.x = *(uint32_t*)&p0; o.y = *(uint32_t*)&p1;
    ((uint2*)g_qbf)[i] = o;
}

// ---------------- main HMMA tile kernel -------------------------------------
// Block tile 128x128, BK=32 bf16, 8 warps (4M x 2N), warp tile 32x64.
// smem rows padded to 80B (32 bf16 + 16B) -> conflict-free ldmatrix.
#define ROWB 80

__global__ void __launch_bounds__(256, 2) tile_kernel() {
    __shared__ __align__(16) char sA[2][128 * ROWB];
    __shared__ __align__(16) char sB[2][128 * ROWB];
    __shared__ float sqi[128], sqj[128];
    __shared__ int   tim[128], tjm[128];
    __shared__ unsigned long long posS[128], negS[128];

    const int tid  = threadIdx.x;
    const int wid  = tid >> 5;
    const int lane = tid & 31;
    const int ib = blockIdx.y * 128;
    const int jb = blockIdx.x * 128;
    const int wm = (wid >> 1) * 32;    // warp M offset (0,32,64,96)
    const int wn = (wid & 1) * 64;     // warp N offset (0,64)

    // meta + accumulator init
    if (tid < 128) {
        sqi[tid] = g_sq[ib + tid];
        tim[tid] = g_tgt[ib + tid];
        sqj[tid] = g_sq[jb + tid];
        tjm[tid] = g_tgt[jb + tid];
        posS[tid] = 0ull;
        negS[tid] = 0ull;
    }

    uint32_t sAu[2], sBu[2];
    sAu[0] = (uint32_t)__cvta_generic_to_shared(&sA[0][0]);
    sAu[1] = (uint32_t)__cvta_generic_to_shared(&sA[1][0]);
    sBu[0] = (uint32_t)__cvta_generic_to_shared(&sB[0][0]);
    sBu[1] = (uint32_t)__cvta_generic_to_shared(&sB[1][0]);

    const uint4* src = (const uint4*)g_qbf;    // 32 uint4 per row
    const int lrow = tid >> 2;       // 0..63 base row per thread (x2 iters)
    const int lc16 = tid & 3;        // 16B chunk within 64B k-slab

    // stage loader: A rows ib+*, B rows jb+*, k offset k0 (elements)
    auto load_stage = [&](int s, int k0) {
        int ku4 = k0 >> 3;
        #pragma unroll
        for (int it = 0; it < 2; it++) {
            int row = lrow + it * 64;
            const uint4* g = src + (size_t)(ib + row) * 32 + ku4 + lc16;
            CP_ASYNC16(sAu[s] + row * ROWB + lc16 * 16, g);
        }
        #pragma unroll
        for (int it = 0; it < 2; it++) {
            int row = lrow + it * 64;
            const uint4* g = src + (size_t)(jb + row) * 32 + ku4 + lc16;
            CP_ASYNC16(sBu[s] + row * ROWB + lc16 * 16, g);
        }
    };

    float acc[2][8][4];
    #pragma unroll
    for (int a = 0; a < 2; a++)
        #pragma unroll
        for (int b = 0; b < 8; b++)
            #pragma unroll
            for (int c = 0; c < 4; c++) acc[a][b][c] = 0.0f;

    // per-thread ldmatrix offsets (within a stage buffer)
    uint32_t offA[2], offB[4];
    #pragma unroll
    for (int tm = 0; tm < 2; tm++) {
        int row = wm + tm * 16 + (lane & 15);
        offA[tm] = row * ROWB + (lane >> 4) * 16;
    }
    #pragma unroll
    for (int tn = 0; tn < 4; tn++) {
        // lanes 0-7: n rows +0..7 @k0 ; 8-15: same rows @k+16B ;
        // 16-23: n rows +8..15 @k0 ; 24-31: same @k+16B
        int row = wn + tn * 16 + (lane & 7) + ((lane & 16) >> 1);
        offB[tn] = row * ROWB + ((lane >> 3) & 1) * 16;
    }

    load_stage(0, 0);
    CP_COMMIT();

    #pragma unroll
    for (int kt = 0; kt < 8; kt++) {
        const int cur = kt & 1;
        if (kt < 7) {
            load_stage(cur ^ 1, (kt + 1) * 32);
            CP_COMMIT();
            CP_WAIT1();
        } else {
            CP_WAIT0();
        }
        __syncthreads();

        #pragma unroll
        for (int k16 = 0; k16 < 2; k16++) {
            uint32_t a[2][4], b[4][4];
            #pragma unroll
            for (int tm = 0; tm < 2; tm++)
                LDSM4(a[tm][0], a[tm][1], a[tm][2], a[tm][3],
                      sAu[cur] + offA[tm] + k16 * 32);
            #pragma unroll
            for (int tn = 0; tn < 4; tn++)
                LDSM4(b[tn][0], b[tn][1], b[tn][2], b[tn][3],
                      sBu[cur] + offB[tn] + k16 * 32);
            #pragma unroll
            for (int tm = 0; tm < 2; tm++)
                #pragma unroll
                for (int tn = 0; tn < 4; tn++) {
                    mma16816(acc[tm][2 * tn],     a[tm][0], a[tm][1], a[tm][2], a[tm][3],
                             b[tn][0], b[tn][1]);
                    mma16816(acc[tm][2 * tn + 1], a[tm][0], a[tm][1], a[tm][2], a[tm][3],
                             b[tn][2], b[tn][3]);
                }
        }
        __syncthreads();
    }

    // ---------------- epilogue: masked per-row argmax ----------------------
    #pragma unroll
    for (int tm = 0; tm < 2; tm++) {
        #pragma unroll
        for (int ro = 0; ro < 2; ro++) {
            int rl = wm + tm * 16 + (lane >> 2) + ro * 8;
            int gi = ib + rl;
            float si = sqi[rl];
            int   tc = tim[rl];
            unsigned long long bp = 0ull, bn = 0ull;
            #pragma unroll
            for (int tn8 = 0; tn8 < 8; tn8++) {
                #pragma unroll
                for (int e = 0; e < 2; e++) {
                    int cl = wn + tn8 * 8 + 2 * (lane & 3) + e;
                    int gj = jb + cl;
                    if (gi == gj) continue;
                    float g = acc[tm][tn8][ro * 2 + e];
                    float dist = fmaf(-2.0f, g, si + sqj[cl]);
                    unsigned long long packed =
                        ((unsigned long long)fkey(dist) << 32) | (unsigned int)(~gj);
                    if (tc == tjm[cl]) { if (packed > bp) bp = packed; }
                    else               { if (packed > bn) bn = packed; }
                }
            }
            #pragma unroll
            for (int o = 1; o <= 2; o <<= 1) {
                unsigned long long tp = __shfl_xor_sync(0xffffffffu, bp, o);
                unsigned long long tn_ = __shfl_xor_sync(0xffffffffu, bn, o);
                if (tp > bp) bp = tp;
                if (tn_ > bn) bn = tn_;
            }
            if ((lane & 3) == 0) {
                if (bp) atomicMax(&posS[rl], bp);
                if (bn) atomicMax(&negS[rl], bn);
            }
        }
    }
    __syncthreads();
    if (tid < 128) {
        if (posS[tid]) atomicMax(&g_pos[ib + tid], posS[tid]);
        if (negS[tid]) atomicMax(&g_neg[ib + tid], negS[tid]);
    }
}

// ---------------- final loss ------------------------------------------------
__global__ void loss_kernel(const float* __restrict__ q, float* __restrict__ out) {
    int gtid = blockIdx.x * blockDim.x + threadIdx.x;
    int warp = gtid >> 5, lane = gtid & 31, wInB = threadIdx.x >> 5;
    __shared__ float bsum[8];
    float loss = 0.0f;
    if (warp < NN) {
        unsigned int pidx = ~(unsigned int)(g_pos[warp] & 0xFFFFFFFFull);
        unsigned int nidx = ~(unsigned int)(g_neg[warp] & 0xFFFFFFFFull);
        const float* qi = q + (size_t)warp * DD;
        const float* qp = q + (size_t)pidx * DD;
        const float* qn = q + (size_t)nidx * DD;
        float dp = 0.0f, dn = 0.0f;
        #pragma unroll
        for (int k = lane; k < DD; k += 32) {
            float x = qi[k];
            float a = x - qp[k]; dp = fmaf(a, a, dp);
            float b = x - qn[k]; dn = fmaf(b, b, dn);
        }
        #pragma unroll
        for (int o = 16; o; o >>= 1) {
            dp += __shfl_xor_sync(0xffffffffu, dp, o);
            dn += __shfl_xor_sync(0xffffffffu, dn, o);
        }
        loss = fmaxf(0.0f, DELTA_F - dp + dn);
    }
    if (lane == 0) bsum[wInB] = loss;
    __syncthreads();
    if (threadIdx.x == 0) {
        float s = 0.0f;
        #pragma unroll
        for (int w = 0; w < 8; w++) s += bsum[w];
        atomicAdd(out, s * (1.0f / (float)NN));
    }
}

// ---------------------------------------------------------------------------
extern "C" void kernel_launch(void* const* d_in, const int* in_sizes, int n_in,
                              void* d_out, int out_size) {
    const float* q   = (const float*)d_in[0];
    const void*  tgt = d_in[1];
    float* out = (float*)d_out;

    zero_kernel<<<1, 1>>>(out);
    prep_kernel<<<NN / 8, 256>>>(q, tgt);
    tgt_kernel<<<NN / 256, 256>>>(tgt);
    qconv_kernel<<<(NN * DD / 4) / 256, 256>>>(q);
    dim3 grid(NN / 128, NN / 128);   // 64 x 64 tiles
    tile_kernel<<<grid, 256>>>();
    loss_kernel<<<NN / 8, 256>>>(q, out);
}

// round 5
// speedup vs baseline: 5.6157x; 1.1208x over previous
#include <cuda_runtime.h>
#include <cuda_bf16.h>
#include <cstdint>

#define NN 8192
#define DD 256
#define DELTA_F 1.0f

// ---------------- device globals (no runtime allocation allowed) ----------
__device__ unsigned long long g_pos[NN];
__device__ unsigned long long g_neg[NN];
__device__ float g_sq[NN];
__device__ int   g_tgt[NN];
__device__ int   g_is32;
__device__ __nv_bfloat16 g_qbf[NN * DD];   // 4MB bf16 copy of queries

// ---------------- helpers ---------------------------------------------------
__device__ __forceinline__ unsigned int fkey(float f) {
    unsigned int u = __float_as_uint(f);
    return (u & 0x80000000u) ? ~u : (u | 0x80000000u);
}

#define CP_ASYNC16(dst, src) \
    asm volatile("cp.async.cg.shared.global [%0], [%1], 16;" :: "r"(dst), "l"(src))
#define CP_COMMIT()  asm volatile("cp.async.commit_group;" ::: "memory")
#define CP_WAIT0()   asm volatile("cp.async.wait_group 0;" ::: "memory")

#define LDSM4(r0, r1, r2, r3, a) \
    asm volatile("ldmatrix.sync.aligned.m8n8.x4.shared.b16 {%0,%1,%2,%3}, [%4];" \
                 : "=r"(r0), "=r"(r1), "=r"(r2), "=r"(r3) : "r"(a))

__device__ __forceinline__ void mma16816(float* c, uint32_t a0, uint32_t a1,
                                         uint32_t a2, uint32_t a3,
                                         uint32_t b0, uint32_t b1) {
    asm volatile("mma.sync.aligned.m16n8k16.row.col.f32.bf16.bf16.f32 "
                 "{%0,%1,%2,%3},{%4,%5,%6,%7},{%8,%9},{%0,%1,%2,%3};"
                 : "+f"(c[0]), "+f"(c[1]), "+f"(c[2]), "+f"(c[3])
                 : "r"(a0), "r"(a1), "r"(a2), "r"(a3), "r"(b0), "r"(b1));
}

__device__ __forceinline__ unsigned long long umax64(unsigned long long a,
                                                     unsigned long long b) {
    return a > b ? a : b;
}

// ---------------- fused prep: zero + sq + bf16 convert + dtype probe --------
__global__ void prep_kernel(const float* __restrict__ q, const void* __restrict__ tgt_raw) {
    int gtid = blockIdx.x * blockDim.x + threadIdx.x;
    int warp = gtid >> 5, lane = gtid & 31;

    if (gtid == 0) g_is32 = 0;                 // relies on launch-order visibility? no:
    // NOTE: is32 is accumulated with atomicOr below and consumed by a LATER kernel.
    // Initialize it here per-run via thread 0 of block 0 is racy vs other blocks' atomicOr.
    // Instead: zero_kernel below does init before this kernel. (kept for clarity)

    if (gtid < NN / 2) {
        int hi = ((const int*)tgt_raw)[2 * gtid + 1];
        if (hi != 0) atomicOr(&g_is32, 1);
    }
    if (warp < NN) {
        const float4* row4 = (const float4*)(q + (size_t)warp * DD);
        uint2* dst = (uint2*)(g_qbf + (size_t)warp * DD);
        float s = 0.0f;
        #pragma unroll
        for (int w = 0; w < 2; w++) {
            int i4 = lane + w * 32;
            float4 v = row4[i4];
            s = fmaf(v.x, v.x, s); s = fmaf(v.y, v.y, s);
            s = fmaf(v.z, v.z, s); s = fmaf(v.w, v.w, s);
            __nv_bfloat162 p0 = __floats2bfloat162_rn(v.x, v.y);
            __nv_bfloat162 p1 = __floats2bfloat162_rn(v.z, v.w);
            uint2 o; o.x = *(uint32_t*)&p0; o.y = *(uint32_t*)&p1;
            dst[i4] = o;
        }
        #pragma unroll
        for (int o = 16; o; o >>= 1) s += __shfl_xor_sync(0xffffffffu, s, o);
        if (lane == 0) {
            g_sq[warp] = s;
            unsigned long long init = ((unsigned long long)0x80000000u << 32) | 0xFFFFFFFFull;
            g_pos[warp] = init;
            g_neg[warp] = init;
        }
    }
}

__global__ void zero_kernel(float* out) { g_is32 = 0; out[0] = 0.0f; }

__global__ void tgt_kernel(const void* __restrict__ tgt_raw) {
    int i = blockIdx.x * blockDim.x + threadIdx.x;
    if (i >= NN) return;
    if (g_is32) g_tgt[i] = ((const int*)tgt_raw)[i];
    else        g_tgt[i] = (int)(((const long long*)tgt_raw)[i]);
}

// ---------------- main HMMA tile kernel (triangular grid) -------------------
// Block tile 128x128, BK=32 bf16, 8 warps (4M x 2N), warp tile 32x64.
// smem rows padded to 80B (32 bf16 + 16B) -> conflict-free ldmatrix.
// Only lower-triangle tiles (bi >= bj) are computed; off-diagonal tiles
// update both the row-side (i) and column-side (j) argmax.
#define ROWB 80

__global__ void __launch_bounds__(256, 2) tile_kernel() {
    __shared__ __align__(16) char sA[2][128 * ROWB];
    __shared__ __align__(16) char sB[2][128 * ROWB];
    __shared__ float sqi[128], sqj[128];
    __shared__ int   tim[128], tjm[128];
    __shared__ unsigned long long posS[128], negS[128];
    __shared__ unsigned long long posC[128], negC[128];

    // triangular decode: blockIdx.x in [0, 2080)
    int t = blockIdx.x;
    int bi = (int)((sqrtf(8.0f * (float)t + 1.0f) - 1.0f) * 0.5f);
    while ((bi + 1) * (bi + 2) / 2 <= t) bi++;
    while (bi * (bi + 1) / 2 > t) bi--;
    int bj = t - bi * (bi + 1) / 2;

    const int tid  = threadIdx.x;
    const int wid  = tid >> 5;
    const int lane = tid & 31;
    const int ib = bi * 128;
    const int jb = bj * 128;
    const bool diag = (bi == bj);
    const int wm = (wid >> 1) * 32;    // warp M offset (0,32,64,96)
    const int wn = (wid & 1) * 64;     // warp N offset (0,64)

    if (tid < 128) {
        sqi[tid] = g_sq[ib + tid];
        tim[tid] = g_tgt[ib + tid];
        sqj[tid] = g_sq[jb + tid];
        tjm[tid] = g_tgt[jb + tid];
        posS[tid] = 0ull; negS[tid] = 0ull;
        posC[tid] = 0ull; negC[tid] = 0ull;
    }

    uint32_t sAu[2], sBu[2];
    sAu[0] = (uint32_t)__cvta_generic_to_shared(&sA[0][0]);
    sAu[1] = (uint32_t)__cvta_generic_to_shared(&sA[1][0]);
    sBu[0] = (uint32_t)__cvta_generic_to_shared(&sB[0][0]);
    sBu[1] = (uint32_t)__cvta_generic_to_shared(&sB[1][0]);

    const uint4* src = (const uint4*)g_qbf;    // 32 uint4 per row
    const int lrow = tid >> 2;       // 0..63 base row (x2 iters)
    const int lc16 = tid & 3;        // 16B chunk in 64B k-slab

    auto load_stage = [&](int s, int k0) {
        int ku4 = k0 >> 3;
        #pragma unroll
        for (int it = 0; it < 2; it++) {
            int row = lrow + it * 64;
            CP_ASYNC16(sAu[s] + row * ROWB + lc16 * 16,
                       src + (size_t)(ib + row) * 32 + ku4 + lc16);
        }
        #pragma unroll
        for (int it = 0; it < 2; it++) {
            int row = lrow + it * 64;
            CP_ASYNC16(sBu[s] + row * ROWB + lc16 * 16,
                       src + (size_t)(jb + row) * 32 + ku4 + lc16);
        }
    };

    float acc[2][8][4];
    #pragma unroll
    for (int a = 0; a < 2; a++)
        #pragma unroll
        for (int b = 0; b < 8; b++)
            #pragma unroll
            for (int c = 0; c < 4; c++) acc[a][b][c] = 0.0f;

    uint32_t offA[2], offB[4];
    #pragma unroll
    for (int tm = 0; tm < 2; tm++) {
        int row = wm + tm * 16 + (lane & 15);
        offA[tm] = row * ROWB + (lane >> 4) * 16;
    }
    #pragma unroll
    for (int tn = 0; tn < 4; tn++) {
        int row = wn + tn * 16 + (lane & 7) + ((lane & 16) >> 1);
        offB[tn] = row * ROWB + ((lane >> 3) & 1) * 16;
    }

    load_stage(0, 0);
    CP_COMMIT();

    #pragma unroll
    for (int kt = 0; kt < 8; kt++) {
        const int cur = kt & 1;
        CP_WAIT0();
        __syncthreads();
        if (kt < 7) { load_stage(cur ^ 1, (kt + 1) * 32); CP_COMMIT(); }

        #pragma unroll
        for (int k16 = 0; k16 < 2; k16++) {
            uint32_t a[2][4], b[4][4];
            #pragma unroll
            for (int tm = 0; tm < 2; tm++)
                LDSM4(a[tm][0], a[tm][1], a[tm][2], a[tm][3],
                      sAu[cur] + offA[tm] + k16 * 32);
            #pragma unroll
            for (int tn = 0; tn < 4; tn++)
                LDSM4(b[tn][0], b[tn][1], b[tn][2], b[tn][3],
                      sBu[cur] + offB[tn] + k16 * 32);
            #pragma unroll
            for (int tm = 0; tm < 2; tm++)
                #pragma unroll
                for (int tn = 0; tn < 4; tn++) {
                    mma16816(acc[tm][2 * tn],     a[tm][0], a[tm][1], a[tm][2], a[tm][3],
                             b[tn][0], b[tn][1]);
                    mma16816(acc[tm][2 * tn + 1], a[tm][0], a[tm][1], a[tm][2], a[tm][3],
                             b[tn][2], b[tn][3]);
                }
        }
    }

    // ---------------- epilogue pass 1: row-side argmax ----------------------
    #pragma unroll
    for (int tm = 0; tm < 2; tm++) {
        #pragma unroll
        for (int ro = 0; ro < 2; ro++) {
            int rl = wm + tm * 16 + (lane >> 2) + ro * 8;
            int gi = ib + rl;
            float si = sqi[rl];
            int   tc = tim[rl];
            unsigned long long bp = 0ull, bn = 0ull;
            #pragma unroll
            for (int tn8 = 0; tn8 < 8; tn8++) {
                #pragma unroll
                for (int e = 0; e < 2; e++) {
                    int cl = wn + tn8 * 8 + 2 * (lane & 3) + e;
                    int gj = jb + cl;
                    if (diag && gi == gj) continue;
                    float dist = fmaf(-2.0f, acc[tm][tn8][ro * 2 + e], si + sqj[cl]);
                    unsigned long long packed =
                        ((unsigned long long)fkey(dist) << 32) | (unsigned int)(~gj);
                    if (tc == tjm[cl]) bp = umax64(bp, packed);
                    else               bn = umax64(bn, packed);
                }
            }
            #pragma unroll
            for (int o = 1; o <= 2; o <<= 1) {
                bp = umax64(bp, __shfl_xor_sync(0xffffffffu, bp, o));
                bn = umax64(bn, __shfl_xor_sync(0xffffffffu, bn, o));
            }
            if ((lane & 3) == 0) {
                if (bp) atomicMax(&posS[rl], bp);
                if (bn) atomicMax(&negS[rl], bn);
            }
        }
    }

    // ---------------- epilogue pass 2: column-side argmax (off-diag only) ---
    if (!diag) {
        #pragma unroll
        for (int tn8 = 0; tn8 < 8; tn8++) {
            #pragma unroll
            for (int e = 0; e < 2; e++) {
                int cl = wn + tn8 * 8 + 2 * (lane & 3) + e;
                float sj = sqj[cl];
                int  tcj = tjm[cl];
                unsigned long long bp = 0ull, bn = 0ull;
                #pragma unroll
                for (int tm = 0; tm < 2; tm++) {
                    #pragma unroll
                    for (int ro = 0; ro < 2; ro++) {
                        int rl = wm + tm * 16 + (lane >> 2) + ro * 8;
                        int gi = ib + rl;
                        float dist = fmaf(-2.0f, acc[tm][tn8][ro * 2 + e], sqi[rl] + sj);
                        unsigned long long packed =
                            ((unsigned long long)fkey(dist) << 32) | (unsigned int)(~gi);
                        if (tim[rl] == tcj) bp = umax64(bp, packed);
                        else                bn = umax64(bn, packed);
                    }
                }
                #pragma unroll
                for (int o = 4; o <= 16; o <<= 1) {
                    bp = umax64(bp, __shfl_xor_sync(0xffffffffu, bp, o));
                    bn = umax64(bn, __shfl_xor_sync(0xffffffffu, bn, o));
                }
                if ((lane >> 2) == 0) {
                    if (bp) atomicMax(&posC[cl], bp);
                    if (bn) atomicMax(&negC[cl], bn);
                }
            }
        }
    }

    __syncthreads();
    if (tid < 128) {
        if (posS[tid]) atomicMax(&g_pos[ib + tid], posS[tid]);
        if (negS[tid]) atomicMax(&g_neg[ib + tid], negS[tid]);
        if (!diag) {
            if (posC[tid]) atomicMax(&g_pos[jb + tid], posC[tid]);
            if (negC[tid]) atomicMax(&g_neg[jb + tid], negC[tid]);
        }
    }
}

// ---------------- final loss ------------------------------------------------
__global__ void loss_kernel(const float* __restrict__ q, float* __restrict__ out) {
    int gtid = blockIdx.x * blockDim.x + threadIdx.x;
    int warp = gtid >> 5, lane = gtid & 31, wInB = threadIdx.x >> 5;
    __shared__ float bsum[8];
    float loss = 0.0f;
    if (warp < NN) {
        unsigned int pidx = ~(unsigned int)(g_pos[warp] & 0xFFFFFFFFull);
        unsigned int nidx = ~(unsigned int)(g_neg[warp] & 0xFFFFFFFFull);
        const float* qi = q + (size_t)warp * DD;
        const float* qp = q + (size_t)pidx * DD;
        const float* qn = q + (size_t)nidx * DD;
        float dp = 0.0f, dn = 0.0f;
        #pragma unroll
        for (int k = lane; k < DD; k += 32) {
            float x = qi[k];
            float a = x - qp[k]; dp = fmaf(a, a, dp);
            float b = x - qn[k]; dn = fmaf(b, b, dn);
        }
        #pragma unroll
        for (int o = 16; o; o >>= 1) {
            dp += __shfl_xor_sync(0xffffffffu, dp, o);
            dn += __shfl_xor_sync(0xffffffffu, dn, o);
        }
        loss = fmaxf(0.0f, DELTA_F - dp + dn);
    }
    if (lane == 0) bsum[wInB] = loss;
    __syncthreads();
    if (threadIdx.x == 0) {
        float s = 0.0f;
        #pragma unroll
        for (int w = 0; w < 8; w++) s += bsum[w];
        atomicAdd(out, s * (1.0f / (float)NN));
    }
}

// ---------------------------------------------------------------------------
extern "C" void kernel_launch(void* const* d_in, const int* in_sizes, int n_in,
                              void* d_out, int out_size) {
    const float* q   = (const float*)d_in[0];
    const void*  tgt = d_in[1];
    float* out = (float*)d_out;

    zero_kernel<<<1, 1>>>(out);
    prep_kernel<<<NN / 8, 256>>>(q, tgt);      // fused sq + bf16 convert + probe + init
    tgt_kernel<<<NN / 256, 256>>>(tgt);
    tile_kernel<<<(64 * 65) / 2, 256>>>();     // 2080 lower-triangle tiles
    loss_kernel<<<NN / 8, 256>>>(q, out);
}

// round 6
// speedup vs baseline: 9.0220x; 1.6066x over previous
#include <cuda_runtime.h>
#include <cuda_bf16.h>
#include <cstdint>

#define NN 8192
#define DD 256
#define DELTA_F 1.0f
#define ROWB 80

// ---------------- device globals (no runtime allocation allowed) ----------
// g_pos/g_neg: u32 key = (dist_bits & ~0x1FFF) | (8191 - index)
__device__ unsigned int g_pos[NN];
__device__ unsigned int g_neg[NN];
__device__ float g_sq[NN];
__device__ int   g_tgt[NN];
__device__ int   g_is32;
__device__ __nv_bfloat16 g_qbf[NN * DD];   // 4MB bf16 copy of queries

// ---------------- helpers ---------------------------------------------------
#define CP_ASYNC16(dst, src) \
    asm volatile("cp.async.cg.shared.global [%0], [%1], 16;" :: "r"(dst), "l"(src))
#define CP_COMMIT()  asm volatile("cp.async.commit_group;" ::: "memory")
#define CP_WAIT0()   asm volatile("cp.async.wait_group 0;" ::: "memory")

#define LDSM4(r0, r1, r2, r3, a) \
    asm volatile("ldmatrix.sync.aligned.m8n8.x4.shared.b16 {%0,%1,%2,%3}, [%4];" \
                 : "=r"(r0), "=r"(r1), "=r"(r2), "=r"(r3) : "r"(a))

__device__ __forceinline__ void mma16816(float* c, uint32_t a0, uint32_t a1,
                                         uint32_t a2, uint32_t a3,
                                         uint32_t b0, uint32_t b1) {
    asm volatile("mma.sync.aligned.m16n8k16.row.col.f32.bf16.bf16.f32 "
                 "{%0,%1,%2,%3},{%4,%5,%6,%7},{%8,%9},{%0,%1,%2,%3};"
                 : "+f"(c[0]), "+f"(c[1]), "+f"(c[2]), "+f"(c[3])
                 : "r"(a0), "r"(a1), "r"(a2), "r"(a3), "r"(b0), "r"(b1));
}

__device__ __forceinline__ uint32_t umax32(uint32_t a, uint32_t b) { return a > b ? a : b; }

// ---------------- small kernels --------------------------------------------
__global__ void zero_kernel(float* out) { g_is32 = 0; out[0] = 0.0f; }

__global__ void prep_kernel(const float* __restrict__ q, const void* __restrict__ tgt_raw) {
    int gtid = blockIdx.x * blockDim.x + threadIdx.x;
    int warp = gtid >> 5, lane = gtid & 31;

    if (gtid < NN / 2) {
        int hi = ((const int*)tgt_raw)[2 * gtid + 1];
        if (hi != 0) atomicOr(&g_is32, 1);
    }
    if (warp < NN) {
        const float4* row4 = (const float4*)(q + (size_t)warp * DD);
        uint2* dst = (uint2*)(g_qbf + (size_t)warp * DD);
        float s = 0.0f;
        #pragma unroll
        for (int w = 0; w < 2; w++) {
            int i4 = lane + w * 32;
            float4 v = row4[i4];
            s = fmaf(v.x, v.x, s); s = fmaf(v.y, v.y, s);
            s = fmaf(v.z, v.z, s); s = fmaf(v.w, v.w, s);
            __nv_bfloat162 p0 = __floats2bfloat162_rn(v.x, v.y);
            __nv_bfloat162 p1 = __floats2bfloat162_rn(v.z, v.w);
            uint2 o; o.x = *(uint32_t*)&p0; o.y = *(uint32_t*)&p1;
            dst[i4] = o;
        }
        #pragma unroll
        for (int o = 16; o; o >>= 1) s += __shfl_xor_sync(0xffffffffu, s, o);
        if (lane == 0) {
            g_sq[warp] = s;
            // key(dist=0, idx=0) = 0 | (8191-0) = 8191
            g_pos[warp] = 8191u;
            g_neg[warp] = 8191u;
        }
    }
}

__global__ void tgt_kernel(const void* __restrict__ tgt_raw) {
    int i = blockIdx.x * blockDim.x + threadIdx.x;
    if (i >= NN) return;
    if (g_is32) g_tgt[i] = ((const int*)tgt_raw)[i];
    else        g_tgt[i] = (int)(((const long long*)tgt_raw)[i]);
}

// ---------------- main HMMA tile kernel (triangular grid) -------------------
__global__ void __launch_bounds__(256, 2) tile_kernel() {
    __shared__ __align__(16) char sA[2][128 * ROWB];
    __shared__ __align__(16) char sB[2][128 * ROWB];
    __shared__ float sqi[128], sqj[128];
    __shared__ int   tim[128], tjm[128];
    __shared__ unsigned int posS[128], negS[128];
    __shared__ unsigned int posC[128], negC[128];

    // triangular decode: blockIdx.x in [0, 2080)
    int t = blockIdx.x;
    int bi = (int)((sqrtf(8.0f * (float)t + 1.0f) - 1.0f) * 0.5f);
    while ((bi + 1) * (bi + 2) / 2 <= t) bi++;
    while (bi * (bi + 1) / 2 > t) bi--;
    int bj = t - bi * (bi + 1) / 2;

    const int tid  = threadIdx.x;
    const int wid  = tid >> 5;
    const int lane = tid & 31;
    const int ib = bi * 128;
    const int jb = bj * 128;
    const bool diag = (bi == bj);
    const int wm = (wid >> 1) * 32;
    const int wn = (wid & 1) * 64;

    if (tid < 128) {
        sqi[tid] = g_sq[ib + tid];
        tim[tid] = g_tgt[ib + tid];
        sqj[tid] = g_sq[jb + tid];
        tjm[tid] = g_tgt[jb + tid];
        posS[tid] = 0u; negS[tid] = 0u;
        posC[tid] = 0u; negC[tid] = 0u;
    }

    uint32_t sAu[2], sBu[2];
    sAu[0] = (uint32_t)__cvta_generic_to_shared(&sA[0][0]);
    sAu[1] = (uint32_t)__cvta_generic_to_shared(&sA[1][0]);
    sBu[0] = (uint32_t)__cvta_generic_to_shared(&sB[0][0]);
    sBu[1] = (uint32_t)__cvta_generic_to_shared(&sB[1][0]);

    // hoisted global src pointers + smem dst addresses
    const uint4* src = (const uint4*)g_qbf;          // 32 uint4 per row
    const int lrow = tid >> 2;                       // 0..63
    const int lc16 = tid & 3;
    const uint4* gA0 = src + (size_t)(ib + lrow) * 32 + lc16;
    const uint4* gA1 = gA0 + 64 * 32;
    const uint4* gB0 = src + (size_t)(jb + lrow) * 32 + lc16;
    const uint4* gB1 = gB0 + 64 * 32;
    uint32_t dA0[2], dA1[2], dB0[2], dB1[2];
    #pragma unroll
    for (int s = 0; s < 2; s++) {
        dA0[s] = sAu[s] + lrow * ROWB + lc16 * 16;
        dA1[s] = dA0[s] + 64 * ROWB;
        dB0[s] = sBu[s] + lrow * ROWB + lc16 * 16;
        dB1[s] = dB0[s] + 64 * ROWB;
    }

    float acc[2][8][4];
    #pragma unroll
    for (int a = 0; a < 2; a++)
        #pragma unroll
        for (int b = 0; b < 8; b++)
            #pragma unroll
            for (int c = 0; c < 4; c++) acc[a][b][c] = 0.0f;

    uint32_t offA[2], offB[4];
    #pragma unroll
    for (int tm = 0; tm < 2; tm++) {
        int row = wm + tm * 16 + (lane & 15);
        offA[tm] = row * ROWB + (lane >> 4) * 16;
    }
    #pragma unroll
    for (int tn = 0; tn < 4; tn++) {
        int row = wn + tn * 16 + (lane & 7) + ((lane & 16) >> 1);
        offB[tn] = row * ROWB + ((lane >> 3) & 1) * 16;
    }

    // stage 0 prefetch (k offset in uint4 units: 4 per 32-element stage)
    CP_ASYNC16(dA0[0], gA0); CP_ASYNC16(dA1[0], gA1);
    CP_ASYNC16(dB0[0], gB0); CP_ASYNC16(dB1[0], gB1);
    CP_COMMIT();

    #pragma unroll
    for (int kt = 0; kt < 8; kt++) {
        const int cur = kt & 1;
        CP_WAIT0();
        __syncthreads();
        if (kt < 7) {
            const int nxt = cur ^ 1;
            const int ko = (kt + 1) * 4;
            CP_ASYNC16(dA0[nxt], gA0 + ko); CP_ASYNC16(dA1[nxt], gA1 + ko);
            CP_ASYNC16(dB0[nxt], gB0 + ko); CP_ASYNC16(dB1[nxt], gB1 + ko);
            CP_COMMIT();
        }
        #pragma unroll
        for (int k16 = 0; k16 < 2; k16++) {
            uint32_t a[2][4], b[4][4];
            #pragma unroll
            for (int tm = 0; tm < 2; tm++)
                LDSM4(a[tm][0], a[tm][1], a[tm][2], a[tm][3],
                      sAu[cur] + offA[tm] + k16 * 32);
            #pragma unroll
            for (int tn = 0; tn < 4; tn++)
                LDSM4(b[tn][0], b[tn][1], b[tn][2], b[tn][3],
                      sBu[cur] + offB[tn] + k16 * 32);
            #pragma unroll
            for (int tm = 0; tm < 2; tm++)
                #pragma unroll
                for (int tn = 0; tn < 4; tn++) {
                    mma16816(acc[tm][2 * tn],     a[tm][0], a[tm][1], a[tm][2], a[tm][3],
                             b[tn][0], b[tn][1]);
                    mma16816(acc[tm][2 * tn + 1], a[tm][0], a[tm][1], a[tm][2], a[tm][3],
                             b[tn][2], b[tn][3]);
                }
        }
    }

    // ---------------- epilogue ----------------------------------------------
    // row slots owned by this thread
    int   rls[4]; float sis[4]; int tcs[4]; uint32_t iinv[4];
    #pragma unroll
    for (int slot = 0; slot < 4; slot++) {
        int tm = slot >> 1, ro = slot & 1;
        int rl = wm + tm * 16 + (lane >> 2) + ro * 8;
        rls[slot] = rl;
        sis[slot] = sqi[rl];
        tcs[slot] = tim[rl];
        iinv[slot] = 8191u - (uint32_t)(ib + rl);
    }
    uint32_t rp[4] = {0u, 0u, 0u, 0u};
    uint32_t rn[4] = {0u, 0u, 0u, 0u};

    if (!diag) {
        // fused: each element updates row-side (key w/ inv col idx) and
        // col-side (key w/ inv row idx)
        #pragma unroll
        for (int tn8 = 0; tn8 < 8; tn8++) {
            #pragma unroll
            for (int e = 0; e < 2; e++) {
                int cl = wn + tn8 * 8 + 2 * (lane & 3) + e;
                float sj = sqj[cl];
                int  tcj = tjm[cl];
                uint32_t jinv = 8191u - (uint32_t)(jb + cl);
                uint32_t cp = 0u, cn = 0u;
                #pragma unroll
                for (int slot = 0; slot < 4; slot++) {
                    int tm = slot >> 1, ro = slot & 1;
                    float dist = fmaf(-2.0f, acc[tm][tn8][ro * 2 + e], sis[slot] + sj);
                    uint32_t hb = __float_as_uint(dist) & 0xFFFFE000u;
                    uint32_t keyr = hb | jinv;
                    uint32_t keyc = hb | iinv[slot];
                    if (tcs[slot] == tcj) {
                        rp[slot] = umax32(rp[slot], keyr);
                        cp = umax32(cp, keyc);
                    } else {
                        rn[slot] = umax32(rn[slot], keyr);
                        cn = umax32(cn, keyc);
                    }
                }
                #pragma unroll
                for (int o = 4; o <= 16; o <<= 1) {
                    cp = umax32(cp, __shfl_xor_sync(0xffffffffu, cp, o));
                    cn = umax32(cn, __shfl_xor_sync(0xffffffffu, cn, o));
                }
                if ((lane >> 2) == 0) {
                    if (cp) atomicMax(&posC[cl], cp);
                    if (cn) atomicMax(&negC[cl], cn);
                }
            }
        }
    } else {
        // diagonal tile: row-side only, exclude self element
        #pragma unroll
        for (int tn8 = 0; tn8 < 8; tn8++) {
            #pragma unroll
            for (int e = 0; e < 2; e++) {
                int cl = wn + tn8 * 8 + 2 * (lane & 3) + e;
                float sj = sqj[cl];
                int  tcj = tjm[cl];
                uint32_t jinv = 8191u - (uint32_t)(jb + cl);
                #pragma unroll
                for (int slot = 0; slot < 4; slot++) {
                    int tm = slot >> 1, ro = slot & 1;
                    if (rls[slot] == cl) continue;   // self (ib==jb)
                    float dist = fmaf(-2.0f, acc[tm][tn8][ro * 2 + e], sis[slot] + sj);
                    uint32_t keyr = (__float_as_uint(dist) & 0xFFFFE000u) | jinv;
                    if (tcs[slot] == tcj) rp[slot] = umax32(rp[slot], keyr);
                    else                  rn[slot] = umax32(rn[slot], keyr);
                }
            }
        }
    }

    // row-side flush: reduce across the 4 lanes of each quad, then smem
    #pragma unroll
    for (int slot = 0; slot < 4; slot++) {
        uint32_t bp = rp[slot], bn = rn[slot];
        #pragma unroll
        for (int o = 1; o <= 2; o <<= 1) {
            bp = umax32(bp, __shfl_xor_sync(0xffffffffu, bp, o));
            bn = umax32(bn, __shfl_xor_sync(0xffffffffu, bn, o));
        }
        if ((lane & 3) == 0) {
            if (bp) atomicMax(&posS[rls[slot]], bp);
            if (bn) atomicMax(&negS[rls[slot]], bn);
        }
    }

    __syncthreads();
    if (tid < 128) {
        if (posS[tid]) atomicMax(&g_pos[ib + tid], posS[tid]);
        if (negS[tid]) atomicMax(&g_neg[ib + tid], negS[tid]);
        if (!diag) {
            if (posC[tid]) atomicMax(&g_pos[jb + tid], posC[tid]);
            if (negC[tid]) atomicMax(&g_neg[jb + tid], negC[tid]);
        }
    }
}

// ---------------- final loss ------------------------------------------------
__global__ void loss_kernel(const float* __restrict__ q, float* __restrict__ out) {
    int gtid = blockIdx.x * blockDim.x + threadIdx.x;
    int warp = gtid >> 5, lane = gtid & 31, wInB = threadIdx.x >> 5;
    __shared__ float bsum[8];
    float loss = 0.0f;
    if (warp < NN) {
        unsigned int pidx = 8191u - (g_pos[warp] & 8191u);
        unsigned int nidx = 8191u - (g_neg[warp] & 8191u);
        const float* qi = q + (size_t)warp * DD;
        const float* qp = q + (size_t)pidx * DD;
        const float* qn = q + (size_t)nidx * DD;
        float dp = 0.0f, dn = 0.0f;
        #pragma unroll
        for (int k = lane; k < DD; k += 32) {
            float x = qi[k];
            float a = x - qp[k]; dp = fmaf(a, a, dp);
            float b = x - qn[k]; dn = fmaf(b, b, dn);
        }
        #pragma unroll
        for (int o = 16; o; o >>= 1) {
            dp += __shfl_xor_sync(0xffffffffu, dp, o);
            dn += __shfl_xor_sync(0xffffffffu, dn, o);
        }
        loss = fmaxf(0.0f, DELTA_F - dp + dn);
    }
    if (lane == 0) bsum[wInB] = loss;
    __syncthreads();
    if (threadIdx.x == 0) {
        float s = 0.0f;
        #pragma unroll
        for (int w = 0; w < 8; w++) s += bsum[w];
        atomicAdd(out, s * (1.0f / (float)NN));
    }
}

// ---------------------------------------------------------------------------
extern "C" void kernel_launch(void* const* d_in, const int* in_sizes, int n_in,
                              void* d_out, int out_size) {
    const float* q   = (const float*)d_in[0];
    const void*  tgt = d_in[1];
    float* out = (float*)d_out;

    zero_kernel<<<1, 1>>>(out);
    prep_kernel<<<NN / 8, 256>>>(q, tgt);
    tgt_kernel<<<NN / 256, 256>>>(tgt);
    tile_kernel<<<(64 * 65) / 2, 256>>>();     // 2080 lower-triangle tiles
    loss_kernel<<<NN / 8, 256>>>(q, out);
}

// round 7
// speedup vs baseline: 9.0287x; 1.0007x over previous
#include <cuda_runtime.h>
#include <cuda_bf16.h>
#include <cstdint>

#define NN 8192
#define DD 256
#define DELTA_F 1.0f
#define ROWB 80
#define STAGE_BYTES 20480          // (128 A rows + 128 B rows) * 80B
#define B_OFF 10240                // B tile offset within a stage
#define NSTAGE 4
#define DYN_BYTES (NSTAGE * STAGE_BYTES)

// ---------------- device globals (no runtime allocation allowed) ----------
// g_pos/g_neg: u32 key = (dist_bits & ~0x1FFF) | (8191 - index)
__device__ unsigned int g_pos[NN];
__device__ unsigned int g_neg[NN];
__device__ float g_sq[NN];
__device__ int   g_tgt[NN];
__device__ int   g_is32;
__device__ __nv_bfloat16 g_qbf[NN * DD];   // 4MB bf16 copy of queries

// ---------------- helpers ---------------------------------------------------
#define CP_ASYNC16(dst, src) \
    asm volatile("cp.async.cg.shared.global [%0], [%1], 16;" :: "r"(dst), "l"(src))
#define CP_COMMIT()  asm volatile("cp.async.commit_group;" ::: "memory")
#define CP_WAIT2()   asm volatile("cp.async.wait_group 2;" ::: "memory")
#define CP_WAIT1()   asm volatile("cp.async.wait_group 1;" ::: "memory")
#define CP_WAIT0()   asm volatile("cp.async.wait_group 0;" ::: "memory")

#define LDSM4(r0, r1, r2, r3, a) \
    asm volatile("ldmatrix.sync.aligned.m8n8.x4.shared.b16 {%0,%1,%2,%3}, [%4];" \
                 : "=r"(r0), "=r"(r1), "=r"(r2), "=r"(r3) : "r"(a))

__device__ __forceinline__ void mma16816(float* c, uint32_t a0, uint32_t a1,
                                         uint32_t a2, uint32_t a3,
                                         uint32_t b0, uint32_t b1) {
    asm volatile("mma.sync.aligned.m16n8k16.row.col.f32.bf16.bf16.f32 "
                 "{%0,%1,%2,%3},{%4,%5,%6,%7},{%8,%9},{%0,%1,%2,%3};"
                 : "+f"(c[0]), "+f"(c[1]), "+f"(c[2]), "+f"(c[3])
                 : "r"(a0), "r"(a1), "r"(a2), "r"(a3), "r"(b0), "r"(b1));
}

__device__ __forceinline__ uint32_t umax32(uint32_t a, uint32_t b) { return a > b ? a : b; }

// ---------------- small kernels --------------------------------------------
__global__ void zero_kernel(float* out) { g_is32 = 0; out[0] = 0.0f; }

__global__ void prep_kernel(const float* __restrict__ q, const void* __restrict__ tgt_raw) {
    int gtid = blockIdx.x * blockDim.x + threadIdx.x;
    int warp = gtid >> 5, lane = gtid & 31;

    if (gtid < NN / 2) {
        int hi = ((const int*)tgt_raw)[2 * gtid + 1];
        if (hi != 0) atomicOr(&g_is32, 1);
    }
    if (warp < NN) {
        const float4* row4 = (const float4*)(q + (size_t)warp * DD);
        uint2* dst = (uint2*)(g_qbf + (size_t)warp * DD);
        float s = 0.0f;
        #pragma unroll
        for (int w = 0; w < 2; w++) {
            int i4 = lane + w * 32;
            float4 v = row4[i4];
            s = fmaf(v.x, v.x, s); s = fmaf(v.y, v.y, s);
            s = fmaf(v.z, v.z, s); s = fmaf(v.w, v.w, s);
            __nv_bfloat162 p0 = __floats2bfloat162_rn(v.x, v.y);
            __nv_bfloat162 p1 = __floats2bfloat162_rn(v.z, v.w);
            uint2 o; o.x = *(uint32_t*)&p0; o.y = *(uint32_t*)&p1;
            dst[i4] = o;
        }
        #pragma unroll
        for (int o = 16; o; o >>= 1) s += __shfl_xor_sync(0xffffffffu, s, o);
        if (lane == 0) {
            g_sq[warp] = s;
            g_pos[warp] = 8191u;   // key(dist=0, idx=0)
            g_neg[warp] = 8191u;
        }
    }
}

__global__ void tgt_kernel(const void* __restrict__ tgt_raw) {
    int i = blockIdx.x * blockDim.x + threadIdx.x;
    if (i >= NN) return;
    if (g_is32) g_tgt[i] = ((const int*)tgt_raw)[i];
    else        g_tgt[i] = (int)(((const long long*)tgt_raw)[i]);
}

// ---------------- main HMMA tile kernel (triangular, 4-stage pipeline) ------
extern __shared__ __align__(16) char dynsm[];

__global__ void __launch_bounds__(256, 2) tile_kernel() {
    __shared__ float sqi[128], sqj[128];
    __shared__ int   tim[128], tjm[128];
    __shared__ unsigned int posS[128], negS[128];
    __shared__ unsigned int posC[128], negC[128];

    // triangular decode: blockIdx.x in [0, 2080)
    int t = blockIdx.x;
    int bi = (int)((sqrtf(8.0f * (float)t + 1.0f) - 1.0f) * 0.5f);
    while ((bi + 1) * (bi + 2) / 2 <= t) bi++;
    while (bi * (bi + 1) / 2 > t) bi--;
    int bj = t - bi * (bi + 1) / 2;

    const int tid  = threadIdx.x;
    const int wid  = tid >> 5;
    const int lane = tid & 31;
    const int ib = bi * 128;
    const int jb = bj * 128;
    const bool diag = (bi == bj);
    const int wm = (wid >> 1) * 32;
    const int wn = (wid & 1) * 64;

    if (tid < 128) {
        sqi[tid] = g_sq[ib + tid];
        tim[tid] = g_tgt[ib + tid];
        sqj[tid] = g_sq[jb + tid];
        tjm[tid] = g_tgt[jb + tid];
        posS[tid] = 0u; negS[tid] = 0u;
        posC[tid] = 0u; negC[tid] = 0u;
    }

    const uint32_t dynb = (uint32_t)__cvta_generic_to_shared(dynsm);

    // hoisted global src pointers + per-thread store offsets
    const uint4* src = (const uint4*)g_qbf;          // 32 uint4 per row
    const int lrow = tid >> 2;                       // 0..63
    const int lc16 = tid & 3;
    const uint4* gA0 = src + (size_t)(ib + lrow) * 32 + lc16;
    const uint4* gA1 = gA0 + 64 * 32;
    const uint4* gB0 = src + (size_t)(jb + lrow) * 32 + lc16;
    const uint4* gB1 = gB0 + 64 * 32;
    const uint32_t aoff0 = lrow * ROWB + lc16 * 16;
    const uint32_t aoff1 = aoff0 + 64 * ROWB;
    const uint32_t boff0 = B_OFF + aoff0;
    const uint32_t boff1 = boff0 + 64 * ROWB;

    auto issue = [&](int buf, int ks) {
        uint32_t sb = dynb + buf * STAGE_BYTES;
        const int ko = ks * 4;                       // 4 uint4 per 32-elem stage
        CP_ASYNC16(sb + aoff0, gA0 + ko);
        CP_ASYNC16(sb + aoff1, gA1 + ko);
        CP_ASYNC16(sb + boff0, gB0 + ko);
        CP_ASYNC16(sb + boff1, gB1 + ko);
    };

    float acc[2][8][4];
    #pragma unroll
    for (int a = 0; a < 2; a++)
        #pragma unroll
        for (int b = 0; b < 8; b++)
            #pragma unroll
            for (int c = 0; c < 4; c++) acc[a][b][c] = 0.0f;

    uint32_t offA[2], offB[4];
    #pragma unroll
    for (int tm = 0; tm < 2; tm++) {
        int row = wm + tm * 16 + (lane & 15);
        offA[tm] = row * ROWB + (lane >> 4) * 16;
    }
    #pragma unroll
    for (int tn = 0; tn < 4; tn++) {
        int row = wn + tn * 16 + (lane & 7) + ((lane & 16) >> 1);
        offB[tn] = B_OFF + row * ROWB + ((lane >> 3) & 1) * 16;
    }

    // prologue: 3 stages in flight
    issue(0, 0); CP_COMMIT();
    issue(1, 1); CP_COMMIT();
    issue(2, 2); CP_COMMIT();

    #pragma unroll
    for (int kt = 0; kt < 8; kt++) {
        const int cur = kt & 3;
        if (kt <= 5)      CP_WAIT2();
        else if (kt == 6) CP_WAIT1();
        else              CP_WAIT0();
        __syncthreads();
        if (kt < 5) { issue((kt + 3) & 3, kt + 3); CP_COMMIT(); }

        const uint32_t sb = dynb + cur * STAGE_BYTES;
        #pragma unroll
        for (int k16 = 0; k16 < 2; k16++) {
            uint32_t a[2][4], b[4][4];
            #pragma unroll
            for (int tm = 0; tm < 2; tm++)
                LDSM4(a[tm][0], a[tm][1], a[tm][2], a[tm][3],
                      sb + offA[tm] + k16 * 32);
            #pragma unroll
            for (int tn = 0; tn < 4; tn++)
                LDSM4(b[tn][0], b[tn][1], b[tn][2], b[tn][3],
                      sb + offB[tn] + k16 * 32);
            #pragma unroll
            for (int tm = 0; tm < 2; tm++)
                #pragma unroll
                for (int tn = 0; tn < 4; tn++) {
                    mma16816(acc[tm][2 * tn],     a[tm][0], a[tm][1], a[tm][2], a[tm][3],
                             b[tn][0], b[tn][1]);
                    mma16816(acc[tm][2 * tn + 1], a[tm][0], a[tm][1], a[tm][2], a[tm][3],
                             b[tn][2], b[tn][3]);
                }
        }
    }

    // ---------------- epilogue ----------------------------------------------
    int   rls[4]; float sis[4]; int tcs[4]; uint32_t iinv[4];
    #pragma unroll
    for (int slot = 0; slot < 4; slot++) {
        int tm = slot >> 1, ro = slot & 1;
        int rl = wm + tm * 16 + (lane >> 2) + ro * 8;
        rls[slot] = rl;
        sis[slot] = sqi[rl];
        tcs[slot] = tim[rl];
        iinv[slot] = 8191u - (uint32_t)(ib + rl);
    }
    uint32_t rp[4] = {0u, 0u, 0u, 0u};
    uint32_t rn[4] = {0u, 0u, 0u, 0u};

    if (!diag) {
        #pragma unroll
        for (int tn8 = 0; tn8 < 8; tn8++) {
            #pragma unroll
            for (int e = 0; e < 2; e++) {
                int cl = wn + tn8 * 8 + 2 * (lane & 3) + e;
                float sj = sqj[cl];
                int  tcj = tjm[cl];
                uint32_t jinv = 8191u - (uint32_t)(jb + cl);
                uint32_t cp = 0u, cn = 0u;
                #pragma unroll
                for (int slot = 0; slot < 4; slot++) {
                    int tm = slot >> 1, ro = slot & 1;
                    float dist = fmaf(-2.0f, acc[tm][tn8][ro * 2 + e], sis[slot] + sj);
                    uint32_t hb = __float_as_uint(dist) & 0xFFFFE000u;
                    uint32_t keyr = hb | jinv;
                    uint32_t keyc = hb | iinv[slot];
                    if (tcs[slot] == tcj) {
                        rp[slot] = umax32(rp[slot], keyr);
                        cp = umax32(cp, keyc);
                    } else {
                        rn[slot] = umax32(rn[slot], keyr);
                        cn = umax32(cn, keyc);
                    }
                }
                #pragma unroll
                for (int o = 4; o <= 16; o <<= 1) {
                    cp = umax32(cp, __shfl_xor_sync(0xffffffffu, cp, o));
                    cn = umax32(cn, __shfl_xor_sync(0xffffffffu, cn, o));
                }
                if ((lane >> 2) == 0) {
                    if (cp) atomicMax(&posC[cl], cp);
                    if (cn) atomicMax(&negC[cl], cn);
                }
            }
        }
    } else {
        #pragma unroll
        for (int tn8 = 0; tn8 < 8; tn8++) {
            #pragma unroll
            for (int e = 0; e < 2; e++) {
                int cl = wn + tn8 * 8 + 2 * (lane & 3) + e;
                float sj = sqj[cl];
                int  tcj = tjm[cl];
                uint32_t jinv = 8191u - (uint32_t)(jb + cl);
                #pragma unroll
                for (int slot = 0; slot < 4; slot++) {
                    int tm = slot >> 1, ro = slot & 1;
                    if (rls[slot] == cl) continue;   // self (ib==jb)
                    float dist = fmaf(-2.0f, acc[tm][tn8][ro * 2 + e], sis[slot] + sj);
                    uint32_t keyr = (__float_as_uint(dist) & 0xFFFFE000u) | jinv;
                    if (tcs[slot] == tcj) rp[slot] = umax32(rp[slot], keyr);
                    else                  rn[slot] = umax32(rn[slot], keyr);
                }
            }
        }
    }

    #pragma unroll
    for (int slot = 0; slot < 4; slot++) {
        uint32_t bp = rp[slot], bn = rn[slot];
        #pragma unroll
        for (int o = 1; o <= 2; o <<= 1) {
            bp = umax32(bp, __shfl_xor_sync(0xffffffffu, bp, o));
            bn = umax32(bn, __shfl_xor_sync(0xffffffffu, bn, o));
        }
        if ((lane & 3) == 0) {
            if (bp) atomicMax(&posS[rls[slot]], bp);
            if (bn) atomicMax(&negS[rls[slot]], bn);
        }
    }

    __syncthreads();
    if (tid < 128) {
        if (posS[tid]) atomicMax(&g_pos[ib + tid], posS[tid]);
        if (negS[tid]) atomicMax(&g_neg[ib + tid], negS[tid]);
        if (!diag) {
            if (posC[tid]) atomicMax(&g_pos[jb + tid], posC[tid]);
            if (negC[tid]) atomicMax(&g_neg[jb + tid], negC[tid]);
        }
    }
}

// ---------------- final loss ------------------------------------------------
__global__ void loss_kernel(const float* __restrict__ q, float* __restrict__ out) {
    int gtid = blockIdx.x * blockDim.x + threadIdx.x;
    int warp = gtid >> 5, lane = gtid & 31, wInB = threadIdx.x >> 5;
    __shared__ float bsum[8];
    float loss = 0.0f;
    if (warp < NN) {
        unsigned int pidx = 8191u - (g_pos[warp] & 8191u);
        unsigned int nidx = 8191u - (g_neg[warp] & 8191u);
        const float* qi = q + (size_t)warp * DD;
        const float* qp = q + (size_t)pidx * DD;
        const float* qn = q + (size_t)nidx * DD;
        float dp = 0.0f, dn = 0.0f;
        #pragma unroll
        for (int k = lane; k < DD; k += 32) {
            float x = qi[k];
            float a = x - qp[k]; dp = fmaf(a, a, dp);
            float b = x - qn[k]; dn = fmaf(b, b, dn);
        }
        #pragma unroll
        for (int o = 16; o; o >>= 1) {
            dp += __shfl_xor_sync(0xffffffffu, dp, o);
            dn += __shfl_xor_sync(0xffffffffu, dn, o);
        }
        loss = fmaxf(0.0f, DELTA_F - dp + dn);
    }
    if (lane == 0) bsum[wInB] = loss;
    __syncthreads();
    if (threadIdx.x == 0) {
        float s = 0.0f;
        #pragma unroll
        for (int w = 0; w < 8; w++) s += bsum[w];
        atomicAdd(out, s * (1.0f / (float)NN));
    }
}

// ---------------------------------------------------------------------------
extern "C" void kernel_launch(void* const* d_in, const int* in_sizes, int n_in,
                              void* d_out, int out_size) {
    const float* q   = (const float*)d_in[0];
    const void*  tgt = d_in[1];
    float* out = (float*)d_out;

    cudaFuncSetAttribute(tile_kernel, cudaFuncAttributeMaxDynamicSharedMemorySize, DYN_BYTES);

    zero_kernel<<<1, 1>>>(out);
    prep_kernel<<<NN / 8, 256>>>(q, tgt);
    tgt_kernel<<<NN / 256, 256>>>(tgt);
    tile_kernel<<<(64 * 65) / 2, 256, DYN_BYTES>>>();   // 2080 lower-triangle tiles
    loss_kernel<<<NN / 8, 256>>>(q, out);
}